// round 16
// baseline (speedup 1.0000x reference)
#include <cuda_runtime.h>
#include <cuda_fp16.h>
#include <cstdint>

constexpr int N_NODES = 50000;
constexpr int DIM     = 256;   // IN == OUT
constexpr int KSEL    = 32;

// ---------------------------------------------------------------------------
// Device-global scratch (allocation-free rule)
// ---------------------------------------------------------------------------
__device__ uint32_t g_topk [(size_t)N_NODES * KSEL]; // packed val(24b)|col(8b)
__device__ uint16_t g_hself[(size_t)N_NODES * DIM];  // h_self (fp16 bits)
__device__ uint16_t g_w [2 * DIM * DIM];             // [Wself;Wneigh] (fp16)

// ---------------------------------------------------------------------------
// helpers
// ---------------------------------------------------------------------------
__device__ __forceinline__ uint32_t smem_u32(const void* p) {
    uint32_t a;
    asm("{ .reg .u64 t; cvta.to.shared.u64 t, %1; cvt.u32.u64 %0, t; }"
        : "=r"(a) : "l"(p));
    return a;
}
__device__ __forceinline__ void cpa16(uint32_t dst, const void* src, bool ok) {
    asm volatile("cp.async.cg.shared.global [%0], [%1], 16, %2;"
                 :: "r"(dst), "l"(src), "r"(ok ? 16 : 0) : "memory");
}
__device__ __forceinline__ void cpa_commit() {
    asm volatile("cp.async.commit_group;" ::: "memory");
}
template <int N>
__device__ __forceinline__ void cpa_wait() {
    asm volatile("cp.async.wait_group %0;" :: "n"(N) : "memory");
}
__device__ __forceinline__ void ldsm4(uint32_t addr, uint32_t r[4]) {
    asm volatile("ldmatrix.sync.aligned.m8n8.x4.shared.b16 {%0,%1,%2,%3}, [%4];"
                 : "=r"(r[0]), "=r"(r[1]), "=r"(r[2]), "=r"(r[3]) : "r"(addr));
}
__device__ __forceinline__ void mma16816(float c[4], const uint32_t a[4],
                                         uint32_t b0, uint32_t b1) {
    asm volatile(
        "mma.sync.aligned.m16n8k16.row.col.f32.f16.f16.f32 "
        "{%0,%1,%2,%3},{%4,%5,%6,%7},{%8,%9},{%0,%1,%2,%3};"
        : "+f"(c[0]), "+f"(c[1]), "+f"(c[2]), "+f"(c[3])
        : "r"(a[0]), "r"(a[1]), "r"(a[2]), "r"(a[3]), "r"(b0), "r"(b1));
}

// ---------------------------------------------------------------------------
// Kernel 0: convert fp32 -> fp16 for the two weight matrices ONLY
// ---------------------------------------------------------------------------
__global__ __launch_bounds__(256)
void splitw_kernel(const float* __restrict__ Wself,
                   const float* __restrict__ Wneigh)
{
    int i = blockIdx.x * blockDim.x + threadIdx.x;  // 0..32767 (float4 units)
    const float* W = (i < 16384) ? Wself : Wneigh;
    int jj = i & 16383;
    float4 v = ((const float4*)W)[jj];
    __half2 h01 = __floats2half2_rn(v.x, v.y);
    __half2 h23 = __floats2half2_rn(v.z, v.w);
    uint2 h;
    h.x = *(uint32_t*)&h01;
    h.y = *(uint32_t*)&h23;
    ((uint2*)g_w)[i] = h;
}

// ---------------------------------------------------------------------------
// Kernel 1: fused fp16 HMMA GEMM + top-k, in-kernel A conversion.
// CTA tile 64x256xK256, BK=32, 256 threads (8 warps), 2 CTAs/SM.
// mat=0: h_self -> g_hself as fp16 (halves DRAM; spmm finishes the add).
// mat=1: feat_neigh+bias -> smem tile -> per-warp top-32 -> packed g_topk.
// ---------------------------------------------------------------------------
constexpr int BM      = 64;                     // CTA row tile
constexpr int RS      = 40;                     // smem row stride (fp16 elems)
constexpr int A_TILE  = BM * RS * 2;            // 5120 B  (one k-tile of A)
constexpr int A16_B   = 8 * A_TILE;             // 40960 B (all 8 k-tiles)
constexpr int B_TILE  = 256 * RS * 2;           // 20480 B
constexpr int NSTAGE  = 3;
constexpr int RS2     = 260;                    // fp32 tile stride (pad 4)
constexpr int TILE_F32 = BM * RS2 * 4;          // 66560 B
constexpr int PIPE_B  = A16_B + NSTAGE * B_TILE;        // 102400 B
constexpr int GEMM_SMEM = (PIPE_B > TILE_F32) ? PIPE_B : TILE_F32; // 102400
constexpr float ERRB  = 1.5e-3f;

__device__ __forceinline__ void load_B(uint32_t slot, int kt, int mat, int tid)
{
    #pragma unroll
    for (int h = 0; h < 4; h++) {   // B: 256 rows x 32 k (1024 chunks of 16B)
        int t = tid + h * 256;
        int row = t >> 2, kc = (t & 3) * 8;
        uint32_t soff = (uint32_t)(row * RS + kc) * 2;
        size_t bidx = (size_t)(mat * DIM + row) * DIM + kt * 32 + kc;
        cpa16(slot + soff, g_w + bidx, true);
    }
}

__global__ __launch_bounds__(256, 2)
void gemm_topk_kernel(const float* __restrict__ feat,
                      const float* __restrict__ Wneigh,
                      const float* __restrict__ bneigh,
                      float* __restrict__ out, int n, int nb)
{
    extern __shared__ char smem[];
    const uint32_t sbase = smem_u32(smem);
    const int tid = threadIdx.x, lane = tid & 31, wid = tid >> 5;
    const int warp_m = wid & 1, warp_n = wid >> 1;   // 2 x 4 warps
    // 1D grid: first nb CTAs -> mat=1 (longer: +topk), rest -> mat=0
    const int bid = blockIdx.x;
    const int mat = (bid < nb) ? 1 : 0;
    const int row0 = ((bid < nb) ? bid : (bid - nb)) * BM;

    // --- B pipeline prologue: stages 0,1 in flight ---
    load_B(sbase + A16_B + 0 * B_TILE, 0, mat, tid); cpa_commit();
    load_B(sbase + A16_B + 1 * B_TILE, 1, mat, tid); cpa_commit();

    // --- A conversion: fp32 feat -> fp16 persistent smem (overlaps B DMA) ---
    {
        const float4* __restrict__ f4 = (const float4*)feat;
        #pragma unroll
        for (int i = 0; i < 16; i++) {
            int idx  = i * 256 + tid;        // float4 index within CTA tile
            int row  = idx >> 6;             // 0..63
            int c4   = idx & 63;             // float4 within row
            int col0 = c4 << 2;              // element col 0..252
            int ktile = col0 >> 5;
            int kk   = col0 & 31;
            int grow = row0 + row;
            uint2 hv = make_uint2(0u, 0u);
            if (grow < n) {
                float4 v = f4[(size_t)grow * 64 + c4];
                __half2 h01 = __floats2half2_rn(v.x, v.y);
                __half2 h23 = __floats2half2_rn(v.z, v.w);
                hv.x = *(uint32_t*)&h01;
                hv.y = *(uint32_t*)&h23;
            }
            *(uint2*)(smem + ktile * A_TILE + (row * RS + kk) * 2) = hv;
        }
    }

    float acc[2][8][4] = {};

    #pragma unroll 1
    for (int kt = 0; kt < 8; kt++) {
        if (kt < 7) cpa_wait<1>(); else cpa_wait<0>();
        __syncthreads();   // stage kt visible; all warps past slot (kt+2)%3 reads
        if (kt < 6) {      // prefetch stage kt+2 into its slot (safe: last read kt-1)
            load_B(sbase + A16_B + ((kt + 2) % NSTAGE) * B_TILE, kt + 2, mat, tid);
            cpa_commit();
        }

        const uint32_t stA = sbase + kt * A_TILE;
        const uint32_t stB = sbase + A16_B + (kt % NSTAGE) * B_TILE;
        #pragma unroll
        for (int ks = 0; ks < 2; ks++) {
            const int k0 = ks * 16;
            uint32_t afr[2][4];
            #pragma unroll
            for (int mf = 0; mf < 2; mf++) {
                uint32_t ra = stA + (uint32_t)((warp_m * 32 + mf * 16 + (lane & 15)) * RS
                                               + k0 + (lane >> 4) * 8) * 2;
                ldsm4(ra, afr[mf]);
            }
            #pragma unroll
            for (int ng = 0; ng < 4; ng++) {
                uint32_t bfr[4];
                uint32_t rb = stB
                    + (uint32_t)((warp_n * 64 + ng * 16 + (lane >> 4) * 8 + (lane & 7)) * RS
                                 + k0 + ((lane >> 3) & 1) * 8) * 2;
                ldsm4(rb, bfr);
                #pragma unroll
                for (int sub = 0; sub < 2; sub++) {
                    int nf = ng * 2 + sub;
                    #pragma unroll
                    for (int mf = 0; mf < 2; mf++)
                        mma16816(acc[mf][nf], afr[mf], bfr[sub * 2], bfr[sub * 2 + 1]);
                }
            }
        }
    }

    if (mat == 0) {
        // h_self -> g_hself as fp16 (spmm adds it into out; halves DRAM)
        #pragma unroll
        for (int nf = 0; nf < 8; nf++) {
            int col = warp_n * 64 + nf * 8 + (lane & 3) * 2;
            #pragma unroll
            for (int mf = 0; mf < 2; mf++) {
                int r0 = row0 + warp_m * 32 + mf * 16 + (lane >> 2);
                if (r0 < n) {
                    __half2 h = __floats2half2_rn(acc[mf][nf][0], acc[mf][nf][1]);
                    *(uint32_t*)(g_hself + (size_t)r0 * DIM + col) = *(uint32_t*)&h;
                }
                int r1 = r0 + 8;
                if (r1 < n) {
                    __half2 h = __floats2half2_rn(acc[mf][nf][2], acc[mf][nf][3]);
                    *(uint32_t*)(g_hself + (size_t)r1 * DIM + col) = *(uint32_t*)&h;
                }
            }
        }
        return;
    }

    // ---- mat == 1: feat_neigh + bias -> smem tile, then fused top-k ----
    __syncthreads();                      // done reading pipeline smem
    float* tile = (float*)smem;
    #pragma unroll
    for (int nf = 0; nf < 8; nf++) {
        int col = warp_n * 64 + nf * 8 + (lane & 3) * 2;
        float2 b = *(const float2*)(bneigh + col);
        #pragma unroll
        for (int mf = 0; mf < 2; mf++) {
            int r0 = warp_m * 32 + mf * 16 + (lane >> 2);
            tile[r0 * RS2 + col]     = acc[mf][nf][0] + b.x;
            tile[r0 * RS2 + col + 1] = acc[mf][nf][1] + b.y;
            int r1 = r0 + 8;
            tile[r1 * RS2 + col]     = acc[mf][nf][2] + b.x;
            tile[r1 * RS2 + col + 1] = acc[mf][nf][3] + b.y;
        }
    }
    __syncthreads();

    // each warp: 8 rows of top-32 (8 warps x 8 rows = 64)
    #pragma unroll 1
    for (int r8 = 0; r8 < 8; r8++) {
        const int lrow = wid * 8 + r8;
        const int grow = row0 + lrow;
        if (grow >= n) break;             // warp-uniform

        const float* srcr = tile + lrow * RS2;
        float v[8]; uint32_t u[8];
        #pragma unroll
        for (int i = 0; i < 8; i++) {
            v[i] = srcr[lane + i * 32];
            uint32_t s = __float_as_uint(v[i]);
            u[i] = (s & 0x80000000u) ? ~s : (s | 0x80000000u);
        }

        // radix select, 2 bits per step (3 parallel REDUXes, early exit)
        uint32_t T = 0;
        #pragma unroll 1
        for (int b = 30; b >= 0; b -= 2) {
            uint32_t c11 = T | (3u << b);
            uint32_t c10 = T | (2u << b);
            uint32_t c01 = T | (1u << b);
            int n11 = 0, n10 = 0, n01 = 0;
            #pragma unroll
            for (int i = 0; i < 8; i++) {
                n11 += (u[i] >= c11);
                n10 += (u[i] >= c10);
                n01 += (u[i] >= c01);
            }
            n11 = __reduce_add_sync(0xffffffffu, n11);
            n10 = __reduce_add_sync(0xffffffffu, n10);
            n01 = __reduce_add_sync(0xffffffffu, n01);
            int chosen = -1;
            if (n11 >= KSEL)      { T = c11; chosen = n11; }
            else if (n10 >= KSEL) { T = c10; chosen = n10; }
            else if (n01 >= KSEL) { T = c01; chosen = n01; }
            if (chosen == KSEL) break;   // unique separation found
        }
        // v32 = approx value of the 32nd largest = min over selected
        float mn = __uint_as_float(0x7f800000);   // +inf
        #pragma unroll
        for (int i = 0; i < 8; i++)
            if (u[i] >= T) mn = fminf(mn, v[i]);
        #pragma unroll
        for (int off = 16; off; off >>= 1)
            mn = fminf(mn, __shfl_xor_sync(0xffffffffu, mn, off));
        const float v32 = mn;
        const float hi_thr = v32 + 2.f * ERRB;
        const float lo_thr = v32 - 2.f * ERRB;

        int cntS = 0, cntB = 0, bm = 0;
        #pragma unroll
        for (int i = 0; i < 8; i++) {
            bool sure = v[i] > hi_thr;
            bool bnd  = !sure && (v[i] >= lo_thr);
            cntS += sure; cntB += bnd;
            if (bnd) bm |= (1 << i);
        }
        cntS = __reduce_add_sync(0xffffffffu, cntS);
        int cntBw = __reduce_add_sync(0xffffffffu, cntB);
        const int need = KSEL - cntS;

        int picked = 0;
        float ex[8];
        const bool exact_path = (cntBw != need);
        if (exact_path) {
            // exact fp32 recompute for boundary elements (rare)
            const float* fr = feat + (size_t)grow * DIM;
            #pragma unroll 1
            for (int i = 0; i < 8; i++) {
                uint32_t bal = __ballot_sync(0xffffffffu, (bm >> i) & 1);
                while (bal) {
                    int owner = __ffs(bal) - 1; bal &= bal - 1;
                    int col = owner + i * 32;
                    const float* wr = Wneigh + (size_t)col * DIM;
                    float p = 0.f;
                    #pragma unroll
                    for (int j = 0; j < 8; j++)
                        p = fmaf(fr[lane + j * 32], wr[lane + j * 32], p);
                    #pragma unroll
                    for (int off = 16; off; off >>= 1)
                        p += __shfl_xor_sync(0xffffffffu, p, off);
                    if (lane == owner) ex[i] = p + bneigh[col];
                }
            }
            int rem = need, avail = bm;
            while (rem > 0) {
                float bv = __uint_as_float(0xff800000);   // -inf
                int bc = 0x7fffffff;
                #pragma unroll
                for (int i = 0; i < 8; i++)
                    if ((avail >> i) & 1) {
                        float e = ex[i]; int c = lane + i * 32;
                        if (e > bv || (e == bv && c < bc)) { bv = e; bc = c; }
                    }
                #pragma unroll
                for (int off = 16; off; off >>= 1) {
                    float ov = __shfl_xor_sync(0xffffffffu, bv, off);
                    int   oc = __shfl_xor_sync(0xffffffffu, bc, off);
                    if (ov > bv || (ov == bv && oc < bc)) { bv = ov; bc = oc; }
                }
                if (lane == (bc & 31)) {
                    avail  &= ~(1 << (bc >> 5));
                    picked |=  (1 << (bc >> 5));
                }
                rem--;
            }
        } else {
            picked = bm;
        }

        // packed compaction write: val(24b rounded) | col(8b)
        const uint32_t ltmask = (1u << lane) - 1u;
        int basep = 0;
        uint32_t* __restrict__ dst = g_topk + (size_t)grow * KSEL;
        #pragma unroll
        for (int i = 0; i < 8; i++) {
            bool sure = v[i] > hi_thr;
            bool pick = (picked >> i) & 1;
            bool sel = sure || pick;
            float wv = (pick && exact_path) ? ex[i] : v[i];
            uint32_t bs = __ballot_sync(0xffffffffu, sel);
            if (sel) {
                int pos = basep + __popc(bs & ltmask);
                uint32_t bits = (__float_as_uint(wv) + 0x80u) & 0xFFFFFF00u;
                dst[pos] = bits | (uint32_t)(lane + i * 32);
            }
            basep += __popc(bs);
        }
    }
}

// ---------------------------------------------------------------------------
// Kernel 2: CSR SpMM — 1 row/warp, single volatile smem accumulator,
// 16-wide edge unroll. Final add pulls h_self from fp16 scratch (no out RMW
// read: out is write-only here -> 51 MB less DRAM traffic).
// ---------------------------------------------------------------------------
__global__ __launch_bounds__(256)
void spmm_kernel(const int* __restrict__ indices,
                 const int* __restrict__ indptr,
                 float* __restrict__ out, int n)
{
    __shared__ float accs[8][DIM];
    const int warp = threadIdx.x >> 5;
    const int lane = threadIdx.x & 31;
    const int row = blockIdx.x * 8 + warp;
    if (row >= n) return;

    volatile float* a = accs[warp];
    #pragma unroll
    for (int i = 0; i < 8; i++) a[lane + i * 32] = 0.f;
    __syncwarp();

    const int s = indptr[row];
    const int e = indptr[row + 1];
    int j = s;
    for (; j + 16 <= e; j += 16) {
        uint32_t p[16];
        #pragma unroll
        for (int t = 0; t < 16; t++)
            p[t] = __ldg(&g_topk[(size_t)indices[j + t] * KSEL + lane]);
        #pragma unroll
        for (int t = 0; t < 16; t++)
            a[p[t] & 0xFF] += __uint_as_float(p[t] & 0xFFFFFF00u);
    }
    if (j + 8 <= e) {
        uint32_t p[8];
        #pragma unroll
        for (int t = 0; t < 8; t++)
            p[t] = __ldg(&g_topk[(size_t)indices[j + t] * KSEL + lane]);
        #pragma unroll
        for (int t = 0; t < 8; t++)
            a[p[t] & 0xFF] += __uint_as_float(p[t] & 0xFFFFFF00u);
        j += 8;
    }
    if (j + 4 <= e) {
        uint32_t p[4];
        #pragma unroll
        for (int t = 0; t < 4; t++)
            p[t] = __ldg(&g_topk[(size_t)indices[j + t] * KSEL + lane]);
        #pragma unroll
        for (int t = 0; t < 4; t++)
            a[p[t] & 0xFF] += __uint_as_float(p[t] & 0xFFFFFF00u);
        j += 4;
    }
    for (; j < e; j++) {
        uint32_t p0 = __ldg(&g_topk[(size_t)indices[j] * KSEL + lane]);
        a[p0 & 0xFF] += __uint_as_float(p0 & 0xFFFFFF00u);
    }
    __syncwarp();

    const uint16_t* __restrict__ hs = g_hself + (size_t)row * DIM;
    #pragma unroll
    for (int i = 0; i < 8; i++) {
        int c = lane + i * 32;
        __half h = *(const __half*)(hs + c);
        out[(size_t)row * DIM + c] = __half2float(h) + a[c];
    }
}

// ---------------------------------------------------------------------------
extern "C" void kernel_launch(void* const* d_in, const int* in_sizes, int n_in,
                              void* d_out, int out_size)
{
    const float* feat    = (const float*)d_in[0];
    const float* Wself   = (const float*)d_in[1];
    const float* Wneigh  = (const float*)d_in[2];
    const float* bneigh  = (const float*)d_in[3];
    const int*   indices = (const int*)d_in[4];
    const int*   indptr  = (const int*)d_in[5];
    float* out = (float*)d_out;

    const int n = in_sizes[0] / DIM;   // 50000

    cudaFuncSetAttribute(gemm_topk_kernel,
                         cudaFuncAttributeMaxDynamicSharedMemorySize, GEMM_SMEM);

    // 0) fp32 -> fp16 conversion (weights only; feat fused into GEMM)
    splitw_kernel<<<128, 256>>>(Wself, Wneigh);

    // 1) fused GEMM + top-k (1D grid, mat=1 first for tail packing; 2 CTA/SM)
    const int nb = (n + BM - 1) / BM;   // 782 per matrix
    gemm_topk_kernel<<<2 * nb, 256, GEMM_SMEM>>>(feat, Wneigh, bneigh, out, n, nb);

    // 2) SpMM: h_neigh + h_self(fp16 scratch) -> out (write-only on out)
    int blocks_rows = (n + 7) / 8;
    spmm_kernel<<<blocks_rows, 256>>>(indices, indptr, out, n);
}

// round 17
// speedup vs baseline: 1.0438x; 1.0438x over previous
#include <cuda_runtime.h>
#include <cuda_fp16.h>
#include <cstdint>

constexpr int N_NODES = 50000;
constexpr int DIM     = 256;   // IN == OUT
constexpr int KSEL    = 32;

// ---------------------------------------------------------------------------
// Device-global scratch (allocation-free rule)
// ---------------------------------------------------------------------------
__device__ uint32_t g_topk[(size_t)N_NODES * KSEL]; // packed val(24b)|col(8b)
__device__ uint16_t g_w [2 * DIM * DIM];            // [Wself;Wneigh] (fp16)

// ---------------------------------------------------------------------------
// helpers
// ---------------------------------------------------------------------------
__device__ __forceinline__ uint32_t smem_u32(const void* p) {
    uint32_t a;
    asm("{ .reg .u64 t; cvta.to.shared.u64 t, %1; cvt.u32.u64 %0, t; }"
        : "=r"(a) : "l"(p));
    return a;
}
__device__ __forceinline__ void cpa16(uint32_t dst, const void* src, bool ok) {
    asm volatile("cp.async.cg.shared.global [%0], [%1], 16, %2;"
                 :: "r"(dst), "l"(src), "r"(ok ? 16 : 0) : "memory");
}
__device__ __forceinline__ void cpa_commit() {
    asm volatile("cp.async.commit_group;" ::: "memory");
}
template <int N>
__device__ __forceinline__ void cpa_wait() {
    asm volatile("cp.async.wait_group %0;" :: "n"(N) : "memory");
}
__device__ __forceinline__ void ldsm4(uint32_t addr, uint32_t r[4]) {
    asm volatile("ldmatrix.sync.aligned.m8n8.x4.shared.b16 {%0,%1,%2,%3}, [%4];"
                 : "=r"(r[0]), "=r"(r[1]), "=r"(r[2]), "=r"(r[3]) : "r"(addr));
}
__device__ __forceinline__ void mma16816(float c[4], const uint32_t a[4],
                                         uint32_t b0, uint32_t b1) {
    asm volatile(
        "mma.sync.aligned.m16n8k16.row.col.f32.f16.f16.f32 "
        "{%0,%1,%2,%3},{%4,%5,%6,%7},{%8,%9},{%0,%1,%2,%3};"
        : "+f"(c[0]), "+f"(c[1]), "+f"(c[2]), "+f"(c[3])
        : "r"(a[0]), "r"(a[1]), "r"(a[2]), "r"(a[3]), "r"(b0), "r"(b1));
}

// ---------------------------------------------------------------------------
// Kernel 0: convert fp32 -> fp16 for the two weight matrices ONLY
// ---------------------------------------------------------------------------
__global__ __launch_bounds__(256)
void splitw_kernel(const float* __restrict__ Wself,
                   const float* __restrict__ Wneigh)
{
    int i = blockIdx.x * blockDim.x + threadIdx.x;  // 0..32767 (float4 units)
    const float* W = (i < 16384) ? Wself : Wneigh;
    int jj = i & 16383;
    float4 v = ((const float4*)W)[jj];
    __half2 h01 = __floats2half2_rn(v.x, v.y);
    __half2 h23 = __floats2half2_rn(v.z, v.w);
    uint2 h;
    h.x = *(uint32_t*)&h01;
    h.y = *(uint32_t*)&h23;
    ((uint2*)g_w)[i] = h;
}

// ---------------------------------------------------------------------------
// Kernel 1: fused fp16 HMMA GEMM + top-k, in-kernel A conversion.
// (round-15 champion structure; out stores + feat reads use streaming hints
//  to protect g_topk / weights L2 residency)
// CTA tile 64x256xK256, BK=32, 256 threads (8 warps), 2 CTAs/SM.
// ---------------------------------------------------------------------------
constexpr int BM      = 64;                     // CTA row tile
constexpr int RS      = 40;                     // smem row stride (fp16 elems)
constexpr int A_TILE  = BM * RS * 2;            // 5120 B  (one k-tile of A)
constexpr int A16_B   = 8 * A_TILE;             // 40960 B (all 8 k-tiles)
constexpr int B_TILE  = 256 * RS * 2;           // 20480 B
constexpr int NSTAGE  = 3;
constexpr int RS2     = 260;                    // fp32 tile stride (pad 4)
constexpr int TILE_F32 = BM * RS2 * 4;          // 66560 B
constexpr int PIPE_B  = A16_B + NSTAGE * B_TILE;        // 102400 B
constexpr int GEMM_SMEM = (PIPE_B > TILE_F32) ? PIPE_B : TILE_F32; // 102400
constexpr float ERRB  = 1.5e-3f;

__device__ __forceinline__ void load_B(uint32_t slot, int kt, int mat, int tid)
{
    #pragma unroll
    for (int h = 0; h < 4; h++) {   // B: 256 rows x 32 k (1024 chunks of 16B)
        int t = tid + h * 256;
        int row = t >> 2, kc = (t & 3) * 8;
        uint32_t soff = (uint32_t)(row * RS + kc) * 2;
        size_t bidx = (size_t)(mat * DIM + row) * DIM + kt * 32 + kc;
        cpa16(slot + soff, g_w + bidx, true);
    }
}

__global__ __launch_bounds__(256, 2)
void gemm_topk_kernel(const float* __restrict__ feat,
                      const float* __restrict__ Wneigh,
                      const float* __restrict__ bneigh,
                      float* __restrict__ out, int n, int nb)
{
    extern __shared__ char smem[];
    const uint32_t sbase = smem_u32(smem);
    const int tid = threadIdx.x, lane = tid & 31, wid = tid >> 5;
    const int warp_m = wid & 1, warp_n = wid >> 1;   // 2 x 4 warps
    // 1D grid: first nb CTAs -> mat=1 (longer: +topk), rest -> mat=0
    const int bid = blockIdx.x;
    const int mat = (bid < nb) ? 1 : 0;
    const int row0 = ((bid < nb) ? bid : (bid - nb)) * BM;

    // --- B pipeline prologue: stages 0,1 in flight ---
    load_B(sbase + A16_B + 0 * B_TILE, 0, mat, tid); cpa_commit();
    load_B(sbase + A16_B + 1 * B_TILE, 1, mat, tid); cpa_commit();

    // --- A conversion: fp32 feat -> fp16 persistent smem (overlaps B DMA) ---
    {
        const float4* __restrict__ f4 = (const float4*)feat;
        #pragma unroll
        for (int i = 0; i < 16; i++) {
            int idx  = i * 256 + tid;        // float4 index within CTA tile
            int row  = idx >> 6;             // 0..63
            int c4   = idx & 63;             // float4 within row
            int col0 = c4 << 2;              // element col 0..252
            int ktile = col0 >> 5;
            int kk   = col0 & 31;
            int grow = row0 + row;
            uint2 hv = make_uint2(0u, 0u);
            if (grow < n) {
                float4 v = __ldcs(&f4[(size_t)grow * 64 + c4]);  // streaming read
                __half2 h01 = __floats2half2_rn(v.x, v.y);
                __half2 h23 = __floats2half2_rn(v.z, v.w);
                hv.x = *(uint32_t*)&h01;
                hv.y = *(uint32_t*)&h23;
            }
            *(uint2*)(smem + ktile * A_TILE + (row * RS + kk) * 2) = hv;
        }
    }

    float acc[2][8][4] = {};

    #pragma unroll 1
    for (int kt = 0; kt < 8; kt++) {
        if (kt < 7) cpa_wait<1>(); else cpa_wait<0>();
        __syncthreads();   // stage kt visible; all warps past slot (kt+2)%3 reads
        if (kt < 6) {      // prefetch stage kt+2 into its slot (safe: last read kt-1)
            load_B(sbase + A16_B + ((kt + 2) % NSTAGE) * B_TILE, kt + 2, mat, tid);
            cpa_commit();
        }

        const uint32_t stA = sbase + kt * A_TILE;
        const uint32_t stB = sbase + A16_B + (kt % NSTAGE) * B_TILE;
        #pragma unroll
        for (int ks = 0; ks < 2; ks++) {
            const int k0 = ks * 16;
            uint32_t afr[2][4];
            #pragma unroll
            for (int mf = 0; mf < 2; mf++) {
                uint32_t ra = stA + (uint32_t)((warp_m * 32 + mf * 16 + (lane & 15)) * RS
                                               + k0 + (lane >> 4) * 8) * 2;
                ldsm4(ra, afr[mf]);
            }
            #pragma unroll
            for (int ng = 0; ng < 4; ng++) {
                uint32_t bfr[4];
                uint32_t rb = stB
                    + (uint32_t)((warp_n * 64 + ng * 16 + (lane >> 4) * 8 + (lane & 7)) * RS
                                 + k0 + ((lane >> 3) & 1) * 8) * 2;
                ldsm4(rb, bfr);
                #pragma unroll
                for (int sub = 0; sub < 2; sub++) {
                    int nf = ng * 2 + sub;
                    #pragma unroll
                    for (int mf = 0; mf < 2; mf++)
                        mma16816(acc[mf][nf], afr[mf], bfr[sub * 2], bfr[sub * 2 + 1]);
                }
            }
        }
    }

    if (mat == 0) {
        // h_self straight to global (fp32, streaming stores)
        #pragma unroll
        for (int nf = 0; nf < 8; nf++) {
            int col = warp_n * 64 + nf * 8 + (lane & 3) * 2;
            #pragma unroll
            for (int mf = 0; mf < 2; mf++) {
                int r0 = row0 + warp_m * 32 + mf * 16 + (lane >> 2);
                if (r0 < n)
                    __stcs((float2*)(out + (size_t)r0 * DIM + col),
                           make_float2(acc[mf][nf][0], acc[mf][nf][1]));
                int r1 = r0 + 8;
                if (r1 < n)
                    __stcs((float2*)(out + (size_t)r1 * DIM + col),
                           make_float2(acc[mf][nf][2], acc[mf][nf][3]));
            }
        }
        return;
    }

    // ---- mat == 1: feat_neigh + bias -> smem tile, then fused top-k ----
    __syncthreads();                      // done reading pipeline smem
    float* tile = (float*)smem;
    #pragma unroll
    for (int nf = 0; nf < 8; nf++) {
        int col = warp_n * 64 + nf * 8 + (lane & 3) * 2;
        float2 b = *(const float2*)(bneigh + col);
        #pragma unroll
        for (int mf = 0; mf < 2; mf++) {
            int r0 = warp_m * 32 + mf * 16 + (lane >> 2);
            tile[r0 * RS2 + col]     = acc[mf][nf][0] + b.x;
            tile[r0 * RS2 + col + 1] = acc[mf][nf][1] + b.y;
            int r1 = r0 + 8;
            tile[r1 * RS2 + col]     = acc[mf][nf][2] + b.x;
            tile[r1 * RS2 + col + 1] = acc[mf][nf][3] + b.y;
        }
    }
    __syncthreads();

    // each warp: 8 rows of top-32 (8 warps x 8 rows = 64)
    #pragma unroll 1
    for (int r8 = 0; r8 < 8; r8++) {
        const int lrow = wid * 8 + r8;
        const int grow = row0 + lrow;
        if (grow >= n) break;             // warp-uniform

        const float* srcr = tile + lrow * RS2;
        float v[8]; uint32_t u[8];
        #pragma unroll
        for (int i = 0; i < 8; i++) {
            v[i] = srcr[lane + i * 32];
            uint32_t s = __float_as_uint(v[i]);
            u[i] = (s & 0x80000000u) ? ~s : (s | 0x80000000u);
        }

        // radix select, 2 bits per step (3 parallel REDUXes, early exit)
        uint32_t T = 0;
        #pragma unroll 1
        for (int b = 30; b >= 0; b -= 2) {
            uint32_t c11 = T | (3u << b);
            uint32_t c10 = T | (2u << b);
            uint32_t c01 = T | (1u << b);
            int n11 = 0, n10 = 0, n01 = 0;
            #pragma unroll
            for (int i = 0; i < 8; i++) {
                n11 += (u[i] >= c11);
                n10 += (u[i] >= c10);
                n01 += (u[i] >= c01);
            }
            n11 = __reduce_add_sync(0xffffffffu, n11);
            n10 = __reduce_add_sync(0xffffffffu, n10);
            n01 = __reduce_add_sync(0xffffffffu, n01);
            int chosen = -1;
            if (n11 >= KSEL)      { T = c11; chosen = n11; }
            else if (n10 >= KSEL) { T = c10; chosen = n10; }
            else if (n01 >= KSEL) { T = c01; chosen = n01; }
            if (chosen == KSEL) break;   // unique separation found
        }
        // v32 = approx value of the 32nd largest = min over selected
        float mn = __uint_as_float(0x7f800000);   // +inf
        #pragma unroll
        for (int i = 0; i < 8; i++)
            if (u[i] >= T) mn = fminf(mn, v[i]);
        #pragma unroll
        for (int off = 16; off; off >>= 1)
            mn = fminf(mn, __shfl_xor_sync(0xffffffffu, mn, off));
        const float v32 = mn;
        const float hi_thr = v32 + 2.f * ERRB;
        const float lo_thr = v32 - 2.f * ERRB;

        int cntS = 0, cntB = 0, bm = 0;
        #pragma unroll
        for (int i = 0; i < 8; i++) {
            bool sure = v[i] > hi_thr;
            bool bnd  = !sure && (v[i] >= lo_thr);
            cntS += sure; cntB += bnd;
            if (bnd) bm |= (1 << i);
        }
        cntS = __reduce_add_sync(0xffffffffu, cntS);
        int cntBw = __reduce_add_sync(0xffffffffu, cntB);
        const int need = KSEL - cntS;

        int picked = 0;
        float ex[8];
        const bool exact_path = (cntBw != need);
        if (exact_path) {
            // exact fp32 recompute for boundary elements (rare)
            const float* fr = feat + (size_t)grow * DIM;
            #pragma unroll 1
            for (int i = 0; i < 8; i++) {
                uint32_t bal = __ballot_sync(0xffffffffu, (bm >> i) & 1);
                while (bal) {
                    int owner = __ffs(bal) - 1; bal &= bal - 1;
                    int col = owner + i * 32;
                    const float* wr = Wneigh + (size_t)col * DIM;
                    float p = 0.f;
                    #pragma unroll
                    for (int j = 0; j < 8; j++)
                        p = fmaf(fr[lane + j * 32], wr[lane + j * 32], p);
                    #pragma unroll
                    for (int off = 16; off; off >>= 1)
                        p += __shfl_xor_sync(0xffffffffu, p, off);
                    if (lane == owner) ex[i] = p + bneigh[col];
                }
            }
            int rem = need, avail = bm;
            while (rem > 0) {
                float bv = __uint_as_float(0xff800000);   // -inf
                int bc = 0x7fffffff;
                #pragma unroll
                for (int i = 0; i < 8; i++)
                    if ((avail >> i) & 1) {
                        float e = ex[i]; int c = lane + i * 32;
                        if (e > bv || (e == bv && c < bc)) { bv = e; bc = c; }
                    }
                #pragma unroll
                for (int off = 16; off; off >>= 1) {
                    float ov = __shfl_xor_sync(0xffffffffu, bv, off);
                    int   oc = __shfl_xor_sync(0xffffffffu, bc, off);
                    if (ov > bv || (ov == bv && oc < bc)) { bv = ov; bc = oc; }
                }
                if (lane == (bc & 31)) {
                    avail  &= ~(1 << (bc >> 5));
                    picked |=  (1 << (bc >> 5));
                }
                rem--;
            }
        } else {
            picked = bm;
        }

        // packed compaction write: val(24b rounded) | col(8b)
        const uint32_t ltmask = (1u << lane) - 1u;
        int basep = 0;
        uint32_t* __restrict__ dst = g_topk + (size_t)grow * KSEL;
        #pragma unroll
        for (int i = 0; i < 8; i++) {
            bool sure = v[i] > hi_thr;
            bool pick = (picked >> i) & 1;
            bool sel = sure || pick;
            float wv = (pick && exact_path) ? ex[i] : v[i];
            uint32_t bs = __ballot_sync(0xffffffffu, sel);
            if (sel) {
                int pos = basep + __popc(bs & ltmask);
                uint32_t bits = (__float_as_uint(wv) + 0x80u) & 0xFFFFFF00u;
                dst[pos] = bits | (uint32_t)(lane + i * 32);
            }
            basep += __popc(bs);
        }
    }
}

// ---------------------------------------------------------------------------
// Kernel 2: CSR SpMM — 1 row/warp, single volatile smem accumulator,
// 16-wide edge unroll. out RMW uses streaming hints (evict-first) so the
// 51 MB out stream doesn't evict g_topk (6.4 MB, gather-hot) from L2.
// ---------------------------------------------------------------------------
__global__ __launch_bounds__(256)
void spmm_kernel(const int* __restrict__ indices,
                 const int* __restrict__ indptr,
                 float* __restrict__ out, int n)
{
    __shared__ float accs[8][DIM];
    const int warp = threadIdx.x >> 5;
    const int lane = threadIdx.x & 31;
    const int row = blockIdx.x * 8 + warp;
    if (row >= n) return;

    volatile float* a = accs[warp];
    #pragma unroll
    for (int i = 0; i < 8; i++) a[lane + i * 32] = 0.f;
    __syncwarp();

    const int s = indptr[row];
    const int e = indptr[row + 1];
    int j = s;
    for (; j + 16 <= e; j += 16) {
        uint32_t p[16];
        #pragma unroll
        for (int t = 0; t < 16; t++)
            p[t] = __ldg(&g_topk[(size_t)indices[j + t] * KSEL + lane]);
        #pragma unroll
        for (int t = 0; t < 16; t++)
            a[p[t] & 0xFF] += __uint_as_float(p[t] & 0xFFFFFF00u);
    }
    if (j + 8 <= e) {
        uint32_t p[8];
        #pragma unroll
        for (int t = 0; t < 8; t++)
            p[t] = __ldg(&g_topk[(size_t)indices[j + t] * KSEL + lane]);
        #pragma unroll
        for (int t = 0; t < 8; t++)
            a[p[t] & 0xFF] += __uint_as_float(p[t] & 0xFFFFFF00u);
        j += 8;
    }
    if (j + 4 <= e) {
        uint32_t p[4];
        #pragma unroll
        for (int t = 0; t < 4; t++)
            p[t] = __ldg(&g_topk[(size_t)indices[j + t] * KSEL + lane]);
        #pragma unroll
        for (int t = 0; t < 4; t++)
            a[p[t] & 0xFF] += __uint_as_float(p[t] & 0xFFFFFF00u);
        j += 4;
    }
    for (; j < e; j++) {
        uint32_t p0 = __ldg(&g_topk[(size_t)indices[j] * KSEL + lane]);
        a[p0 & 0xFF] += __uint_as_float(p0 & 0xFFFFFF00u);
    }
    __syncwarp();

    #pragma unroll
    for (int i = 0; i < 8; i++) {
        int c = lane + i * 32;
        float* p = out + (size_t)row * DIM + c;
        __stcs(p, __ldcs(p) + a[c]);   // streaming RMW (evict-first)
    }
}

// ---------------------------------------------------------------------------
extern "C" void kernel_launch(void* const* d_in, const int* in_sizes, int n_in,
                              void* d_out, int out_size)
{
    const float* feat    = (const float*)d_in[0];
    const float* Wself   = (const float*)d_in[1];
    const float* Wneigh  = (const float*)d_in[2];
    const float* bneigh  = (const float*)d_in[3];
    const int*   indices = (const int*)d_in[4];
    const int*   indptr  = (const int*)d_in[5];
    float* out = (float*)d_out;

    const int n = in_sizes[0] / DIM;   // 50000

    cudaFuncSetAttribute(gemm_topk_kernel,
                         cudaFuncAttributeMaxDynamicSharedMemorySize, GEMM_SMEM);

    // 0) fp32 -> fp16 conversion (weights only; feat fused into GEMM)
    splitw_kernel<<<128, 256>>>(Wself, Wneigh);

    // 1) fused GEMM + top-k (1D grid, mat=1 first for tail packing; 2 CTA/SM)
    const int nb = (n + BM - 1) / BM;   // 782 per matrix
    gemm_topk_kernel<<<2 * nb, 256, GEMM_SMEM>>>(feat, Wneigh, bneigh, out, n, nb);

    // 2) SpMM accumulate onto h_self (1 row/warp, 16-wide unroll)
    int blocks_rows = (n + 7) / 8;
    spmm_kernel<<<blocks_rows, 256>>>(indices, indptr, out, n);
}